// round 1
// baseline (speedup 1.0000x reference)
#include <cuda_runtime.h>
#include <cstdint>
#include <cstddef>

// ---------------- problem constants ----------------
#define T_LEN 512
#define BATCH 32
#define H_DIM 512
#define G_ROWS 2048                     // 4*H
#define M_TOT (T_LEN * BATCH)           // 16384
#define OUT_OUTPUTS_OFF 0
#define OUT_HIDDEN_OFF  16777216        // T*B*2*H
#define OUT_EMB_OFF     33554432        // + 2*T*B*H
#define NBLK 128                        // recurrence blocks (<= SM count)

// ---------------- device scratch (static: no runtime allocation) ----------------
// G[dir][t][row][b]  : gate preactivations  (2*512*2048*32 floats = 268 MB)
__device__ float g_G[(size_t)2 * T_LEN * G_ROWS * BATCH];
// h state double buffer: [dir][parity][u][b]
__device__ float g_h[2 * 2 * H_DIM * BATCH];
// barrier flags
__device__ int g_flags[NBLK];

// ---------------- init: zero state + flags (must run every launch) ----------------
__global__ void init_kernel() {
    int tid = blockIdx.x * blockDim.x + threadIdx.x;
    if (tid < 2 * 2 * H_DIM * BATCH) g_h[tid] = 0.0f;
    if (tid < NBLK) g_flags[tid] = 0;
}

// ---------------- embedded output: gather ----------------
__global__ void embed_kernel(const int* __restrict__ seq,
                             const float* __restrict__ emb,
                             float* __restrict__ out_emb) {
    int i = blockIdx.x * blockDim.x + threadIdx.x;   // over M_TOT * 128 float4s
    int m = i >> 7;
    int hq = (i & 127) << 2;
    int row = __ldg(seq + m);
    float4 v = *(const float4*)(emb + (size_t)row * H_DIM + hq);
    *(float4*)(out_emb + (size_t)m * H_DIM + hq) = v;
}

// ---------------- input-projection GEMM: G = x @ Wih^T + (bih+bhh) ----------------
// C[m][n], m = t*32+b over 16384, n over 2048, K=512. A row = emb[seq[m]].
__global__ __launch_bounds__(256) void xproj_kernel(
    const int* __restrict__ seq, const float* __restrict__ emb,
    const float* __restrict__ Wf, const float* __restrict__ Wb,
    const float* __restrict__ bihf, const float* __restrict__ bhhf,
    const float* __restrict__ bihb, const float* __restrict__ bhhb) {
    int dir = blockIdx.z;
    const float* W  = dir ? Wb : Wf;
    const float* b1 = dir ? bihb : bihf;
    const float* b2 = dir ? bhhb : bhhf;
    int n0 = blockIdx.x * 64;
    int m0 = blockIdx.y * 64;

    __shared__ float As[16][68];
    __shared__ float Bs[16][68];
    __shared__ int idxs[64];

    int tid = threadIdx.x;
    if (tid < 64) idxs[tid] = seq[m0 + tid];
    __syncthreads();

    float acc[4][4];
#pragma unroll
    for (int i = 0; i < 4; i++)
#pragma unroll
        for (int j = 0; j < 4; j++) acc[i][j] = 0.0f;

    int lr = tid >> 2;          // 0..63 : tile row
    int lk = (tid & 3) * 4;     // 0,4,8,12 : k quad
    int ty = tid >> 4;          // 0..15 : m group
    int tx = tid & 15;          // 0..15 : n group

    for (int k0 = 0; k0 < H_DIM; k0 += 16) {
        float4 a = *(const float4*)(emb + (size_t)idxs[lr] * H_DIM + k0 + lk);
        float4 w = *(const float4*)(W + (size_t)(n0 + lr) * H_DIM + k0 + lk);
        As[lk + 0][lr] = a.x; As[lk + 1][lr] = a.y;
        As[lk + 2][lr] = a.z; As[lk + 3][lr] = a.w;
        Bs[lk + 0][lr] = w.x; Bs[lk + 1][lr] = w.y;
        Bs[lk + 2][lr] = w.z; Bs[lk + 3][lr] = w.w;
        __syncthreads();
#pragma unroll
        for (int kk = 0; kk < 16; kk++) {
            float4 av = *(const float4*)&As[kk][ty * 4];
            float4 bv = *(const float4*)&Bs[kk][tx * 4];
            float aa[4] = {av.x, av.y, av.z, av.w};
            float bbv[4] = {bv.x, bv.y, bv.z, bv.w};
#pragma unroll
            for (int i = 0; i < 4; i++)
#pragma unroll
                for (int j = 0; j < 4; j++) acc[i][j] += aa[i] * bbv[j];
        }
        __syncthreads();
    }

    // epilogue: write G[dir][t][n][b] with float4 over 4 consecutive b
    int m = m0 + ty * 4;
    int t = m >> 5;
    int b = m & 31;            // multiple of 4; same t for all 4 rows
#pragma unroll
    for (int j = 0; j < 4; j++) {
        int n = n0 + tx * 4 + j;
        float bias = __ldg(b1 + n) + __ldg(b2 + n);
        float4 v = make_float4(acc[0][j] + bias, acc[1][j] + bias,
                               acc[2][j] + bias, acc[3][j] + bias);
        *(float4*)(g_G + ((size_t)(dir * T_LEN + t) * G_ROWS + n) * BATCH + b) = v;
    }
}

// ---------------- activations ----------------
__device__ __forceinline__ float fsig(float x) {
    return __fdividef(1.0f, 1.0f + __expf(-x));
}
__device__ __forceinline__ float ftanh(float x) {
    x = fminf(fmaxf(x, -15.0f), 15.0f);
    float e = __expf(-2.0f * x);
    return __fdividef(1.0f - e, 1.0f + e);
}

// ---------------- persistent recurrence kernel ----------------
// 128 blocks: blocks 0..63 forward, 64..127 backward. Block owns 8 hidden
// units (32 gate rows), Whh slice resident in smem, c in registers.
// smem floats: w_s 512*32 | h_s 512*32 | part 4*32*33 | out_s 8*33 | len 32
#define SM_W   0
#define SM_H   (512 * 32)
#define SM_P   (2 * 512 * 32)
#define SM_O   (SM_P + 4 * 32 * 33)
#define SM_L   (SM_O + 8 * 33)
#define SMEM_FLOATS (SM_L + 32)
#define SMEM_BYTES (SMEM_FLOATS * 4)

__global__ void __launch_bounds__(256, 1) lstm_rec(
    const float* __restrict__ Whh_f, const float* __restrict__ Whh_b,
    const int* __restrict__ lengths, float* __restrict__ out) {
    extern __shared__ float sm[];
    float* w_s = sm + SM_W;     // [k][r_local]  k=0..511, r=0..31
    float* h_s = sm + SM_H;     // [k][b]
    float* part = sm + SM_P;    // [kc][r][b] padded 33
    float* out_s = sm + SM_O;   // [uj][b] padded 33
    int* len_s = (int*)(sm + SM_L);

    int tid = threadIdx.x;
    int bk = blockIdx.x;
    int dir = bk >> 6;
    int u0 = (bk & 63) * 8;
    const float* Whh = dir ? Whh_b : Whh_f;

    if (tid < 32) len_s[tid] = lengths[tid];
    // stage Whh slice transposed into smem (one-time)
    for (int r = 0; r < 32; r++) {
        int grow = ((r >> 3) << 9) + u0 + (r & 7);   // q*512 + u0 + uj
        const float* src = Whh + (size_t)grow * H_DIM;
        for (int k = tid; k < H_DIM; k += 256) w_s[k * 32 + r] = src[k];
    }
    __syncthreads();

    // GEMM thread roles: split-K(4) x rows(8 groups of 4) x batch(8 groups of 4)
    int kc = tid >> 6;
    int r0 = ((tid >> 3) & 7) * 4;
    int b0 = (tid & 7) * 4;
    // combine roles
    int uj = tid >> 5;
    int bb = tid & 31;
    int myu = u0 + uj;
    int mylen = 0;
    float c_reg = 0.0f;

    float* hb_base = g_h + dir * 2 * (H_DIM * BATCH);
    volatile int* vf = g_flags;

    __syncthreads();
    mylen = len_s[bb];

    for (int s = 0; s < T_LEN; s++) {
        int t = dir ? (T_LEN - 1 - s) : s;
        int p = s & 1;

        // stage h state (bypass L1: buffer rewritten by other SMs)
        {
            const float4* hin = (const float4*)(hb_base + p * (H_DIM * BATCH));
            float4* hs4 = (float4*)h_s;
#pragma unroll
            for (int i = 0; i < 16; i++)
                hs4[tid + i * 256] = __ldcg(hin + tid + i * 256);
        }
        __syncthreads();

        // 32 rows x 32 batches x 512 K GEMM from smem
        float acc[4][4];
#pragma unroll
        for (int i = 0; i < 4; i++)
#pragma unroll
            for (int j = 0; j < 4; j++) acc[i][j] = 0.0f;
        {
            const float* wp = w_s + (kc << 7) * 32;
            const float* hp = h_s + (kc << 7) * 32;
#pragma unroll 4
            for (int k = 0; k < 128; k++) {
                float4 wv = *(const float4*)(wp + k * 32 + r0);
                float4 hv = *(const float4*)(hp + k * 32 + b0);
                float wa[4] = {wv.x, wv.y, wv.z, wv.w};
                float ha[4] = {hv.x, hv.y, hv.z, hv.w};
#pragma unroll
                for (int i = 0; i < 4; i++)
#pragma unroll
                    for (int j = 0; j < 4; j++) acc[i][j] += wa[i] * ha[j];
            }
        }
#pragma unroll
        for (int i = 0; i < 4; i++)
#pragma unroll
            for (int j = 0; j < 4; j++)
                part[((kc << 5) + r0 + i) * 33 + (b0 + j)] = acc[i][j];
        __syncthreads();

        // gate combine for (unit uj, batch bb)
        {
            const float* Gp = g_G + (size_t)(dir * T_LEN + t) * G_ROWS * BATCH;
            float sarr[4];
#pragma unroll
            for (int q = 0; q < 4; q++) {
                int r = q * 8 + uj;
                float v = part[r * 33 + bb] + part[(32 + r) * 33 + bb] +
                          part[(64 + r) * 33 + bb] + part[(96 + r) * 33 + bb];
                v += __ldg(Gp + (size_t)(q * 512 + myu) * BATCH + bb);
                sarr[q] = v;
            }
            float ig = fsig(sarr[0]);
            float fg = fsig(sarr[1]);
            float gg = ftanh(sarr[2]);
            float og = fsig(sarr[3]);
            float cn = fg * c_reg + ig * gg;
            float hn = og * ftanh(cn);
            bool m = (t < mylen);
            c_reg = m ? cn : c_reg;
            float hold = h_s[myu * 32 + bb];
            float hsel = m ? hn : hold;
            __stcg(hb_base + (p ^ 1) * (H_DIM * BATCH) + myu * 32 + bb, hsel);
            out_s[uj * 33 + bb] = m ? hn : 0.0f;
        }
        __syncthreads();

        // coalesced output write (outputs + hidden_states)
        {
            int b2 = tid >> 3;
            int uj2 = tid & 7;
            float val = out_s[uj2 * 33 + b2];
            int u2 = u0 + uj2;
            out[OUT_OUTPUTS_OFF + ((size_t)(t * BATCH + b2) * 2 + dir) * H_DIM + u2] = val;
            out[OUT_HIDDEN_OFF + ((size_t)(dir * T_LEN + t) * BATCH + b2) * H_DIM + u2] = val;
        }

        // grid barrier: fence, publish flag, poll all flags
        __threadfence();
        __syncthreads();
        if (tid == 0) vf[bk] = s + 1;
        if (tid < 32) {
            int need = s + 1;
            for (;;) {
                int a = vf[tid];
                int b_ = vf[tid + 32];
                int c_ = vf[tid + 64];
                int d_ = vf[tid + 96];
                if (a >= need && b_ >= need && c_ >= need && d_ >= need) break;
            }
        }
        __syncthreads();
    }
}

// ---------------- launch ----------------
extern "C" void kernel_launch(void* const* d_in, const int* in_sizes, int n_in,
                              void* d_out, int out_size) {
    const int* seq     = (const int*)d_in[0];
    const int* lens    = (const int*)d_in[1];
    const float* emb   = (const float*)d_in[2];
    const float* Wih_f = (const float*)d_in[3];
    const float* Whh_f = (const float*)d_in[4];
    const float* bih_f = (const float*)d_in[5];
    const float* bhh_f = (const float*)d_in[6];
    const float* Wih_b = (const float*)d_in[7];
    const float* Whh_b = (const float*)d_in[8];
    const float* bih_b = (const float*)d_in[9];
    const float* bhh_b = (const float*)d_in[10];
    float* out = (float*)d_out;

    init_kernel<<<256, 256>>>();
    embed_kernel<<<(M_TOT * 128) / 256, 256>>>(seq, emb, out + OUT_EMB_OFF);
    xproj_kernel<<<dim3(G_ROWS / 64, M_TOT / 64, 2), 256>>>(
        seq, emb, Wih_f, Wih_b, bih_f, bhh_f, bih_b, bhh_b);
    cudaFuncSetAttribute(lstm_rec, cudaFuncAttributeMaxDynamicSharedMemorySize,
                         SMEM_BYTES);
    lstm_rec<<<NBLK, 256, SMEM_BYTES>>>(Whh_f, Whh_b, lens, out);
}

// round 3
// speedup vs baseline: 1.1554x; 1.1554x over previous
#include <cuda_runtime.h>
#include <cuda_bf16.h>
#include <cstdint>
#include <cstddef>

// ---------------- problem constants ----------------
#define T_LEN 512
#define BATCH 32
#define H_DIM 512
#define G_ROWS 2048                     // 4*H
#define M_TOT (T_LEN * BATCH)           // 16384
#define OUT_OUTPUTS_OFF 0
#define OUT_HIDDEN_OFF  16777216        // T*B*2*H
#define OUT_EMB_OFF     33554432        // + 2*T*B*H
#define NBLK 128                        // recurrence blocks (<= SM count)
#define HFRAG 16384                     // h fragment elements per (dir,parity)

// ---------------- device scratch ----------------
__device__ float g_G[(size_t)2 * T_LEN * G_ROWS * BATCH];   // gate preactivations
__device__ __align__(16) float g_hhi[2 * 2 * HFRAG];        // h hi (tf32-rounded fp32), frag layout
__device__ __align__(16) __nv_bfloat16 g_hlo[2 * 2 * HFRAG];// h lo (bf16), frag layout
__device__ int g_flags[NBLK];                               // per-block step flags

// ---------------- init ----------------
__global__ void init_kernel() {
    int tid = blockIdx.x * blockDim.x + threadIdx.x;
    if (tid < 2 * 2 * HFRAG) {
        g_hhi[tid] = 0.0f;
        g_hlo[tid] = __float2bfloat16(0.0f);
    }
    if (tid < NBLK) g_flags[tid] = 0;
}

// ---------------- embedded output: gather ----------------
__global__ void embed_kernel(const int* __restrict__ seq,
                             const float* __restrict__ emb,
                             float* __restrict__ out_emb) {
    int i = blockIdx.x * blockDim.x + threadIdx.x;
    int m = i >> 7;
    int hq = (i & 127) << 2;
    int row = __ldg(seq + m);
    float4 v = *(const float4*)(emb + (size_t)row * H_DIM + hq);
    *(float4*)(out_emb + (size_t)m * H_DIM + hq) = v;
}

// ---------------- input-projection GEMM: G = x @ Wih^T + (bih+bhh) ----------------
__global__ __launch_bounds__(256) void xproj_kernel(
    const int* __restrict__ seq, const float* __restrict__ emb,
    const float* __restrict__ Wf, const float* __restrict__ Wb,
    const float* __restrict__ bihf, const float* __restrict__ bhhf,
    const float* __restrict__ bihb, const float* __restrict__ bhhb) {
    int dir = blockIdx.z;
    const float* W  = dir ? Wb : Wf;
    const float* b1 = dir ? bihb : bihf;
    const float* b2 = dir ? bhhb : bhhf;
    int n0 = blockIdx.x * 64;
    int m0 = blockIdx.y * 64;

    __shared__ float As[16][68];
    __shared__ float Bs[16][68];
    __shared__ int idxs[64];

    int tid = threadIdx.x;
    if (tid < 64) idxs[tid] = seq[m0 + tid];
    __syncthreads();

    float acc[4][4];
#pragma unroll
    for (int i = 0; i < 4; i++)
#pragma unroll
        for (int j = 0; j < 4; j++) acc[i][j] = 0.0f;

    int lr = tid >> 2;
    int lk = (tid & 3) * 4;
    int ty = tid >> 4;
    int tx = tid & 15;

    for (int k0 = 0; k0 < H_DIM; k0 += 16) {
        float4 a = *(const float4*)(emb + (size_t)idxs[lr] * H_DIM + k0 + lk);
        float4 w = *(const float4*)(W + (size_t)(n0 + lr) * H_DIM + k0 + lk);
        As[lk + 0][lr] = a.x; As[lk + 1][lr] = a.y;
        As[lk + 2][lr] = a.z; As[lk + 3][lr] = a.w;
        Bs[lk + 0][lr] = w.x; Bs[lk + 1][lr] = w.y;
        Bs[lk + 2][lr] = w.z; Bs[lk + 3][lr] = w.w;
        __syncthreads();
#pragma unroll
        for (int kk = 0; kk < 16; kk++) {
            float4 av = *(const float4*)&As[kk][ty * 4];
            float4 bv = *(const float4*)&Bs[kk][tx * 4];
            float aa[4] = {av.x, av.y, av.z, av.w};
            float bbv[4] = {bv.x, bv.y, bv.z, bv.w};
#pragma unroll
            for (int i = 0; i < 4; i++)
#pragma unroll
                for (int j = 0; j < 4; j++) acc[i][j] += aa[i] * bbv[j];
        }
        __syncthreads();
    }

    int m = m0 + ty * 4;
    int t = m >> 5;
    int b = m & 31;
#pragma unroll
    for (int j = 0; j < 4; j++) {
        int n = n0 + tx * 4 + j;
        float bias = __ldg(b1 + n) + __ldg(b2 + n);
        float4 v = make_float4(acc[0][j] + bias, acc[1][j] + bias,
                               acc[2][j] + bias, acc[3][j] + bias);
        *(float4*)(g_G + ((size_t)(dir * T_LEN + t) * G_ROWS + n) * BATCH + b) = v;
    }
}

// ---------------- helpers ----------------
__device__ __forceinline__ float fsig(float x) {
    return __fdividef(1.0f, 1.0f + __expf(-x));
}
__device__ __forceinline__ float ftanh(float x) {
    x = fminf(fmaxf(x, -15.0f), 15.0f);
    float e = __expf(-2.0f * x);
    return __fdividef(1.0f - e, 1.0f + e);
}
__device__ __forceinline__ float tf32_hi(float x) {
    unsigned u;
    asm("cvt.rna.tf32.f32 %0, %1;" : "=r"(u) : "f"(x));
    return __uint_as_float(u);
}
__device__ __forceinline__ void mma_tf32(float& c0, float& c1, float& c2, float& c3,
                                         float a0, float a1, float a2, float a3,
                                         float b0, float b1) {
    asm volatile(
        "mma.sync.aligned.m16n8k8.row.col.f32.tf32.tf32.f32 "
        "{%0,%1,%2,%3}, {%4,%5,%6,%7}, {%8,%9}, {%0,%1,%2,%3};\n"
        : "+f"(c0), "+f"(c1), "+f"(c2), "+f"(c3)
        : "r"(__float_as_uint(a0)), "r"(__float_as_uint(a1)),
          "r"(__float_as_uint(a2)), "r"(__float_as_uint(a3)),
          "r"(__float_as_uint(b0)), "r"(__float_as_uint(b1)));
}

// ---------------- persistent recurrence kernel (tensor-core) ----------------
// smem layout (float units)
#define SM_WHI  0                        // 16384 f  : W hi fragments
#define SM_HHI  16384                    // 16384 f  : h hi fragments
#define SM_WLO  32768                    // 8192 f   : W lo fragments (bf16 x 16384)
#define SM_HLO  40960                    // 8192 f   : h lo fragments (bf16 x 16384)
#define SM_PART 49152                    // 32*33 f  : C tiles
#define SM_OUT  (SM_PART + 32 * 33)      // 8*33 f
#define SM_LEN  (SM_OUT + 8 * 33)        // 32 ints
#define SMEM_FLOATS (SM_LEN + 32)
#define SMEM_BYTES (SMEM_FLOATS * 4)

__global__ void __launch_bounds__(256, 1) lstm_rec(
    const float* __restrict__ Whh_f, const float* __restrict__ Whh_b,
    const int* __restrict__ lengths, float* __restrict__ out) {
    extern __shared__ float sm[];
    float* w_hi_s = sm + SM_WHI;
    float* h_hi_s = sm + SM_HHI;
    float* w_lo_s = sm + SM_WLO;   // viewed as bf16 / uint2
    float* h_lo_s = sm + SM_HLO;   // viewed as bf16 / uint
    float* part   = sm + SM_PART;  // [r][b] padded 33
    float* out_s  = sm + SM_OUT;   // [uj][b] padded 33
    int*   len_s  = (int*)(sm + SM_LEN);

    int tid = threadIdx.x;
    int bk = blockIdx.x;
    int dir = bk >> 6;
    int u0 = (bk & 63) * 8;
    const float* Whh = dir ? Whh_b : Whh_f;

    if (tid < 32) len_s[tid] = lengths[tid];

    // ---- one-time: build W fragments (hi fp32 tf32-rounded, lo bf16) ----
    // layout: [mt(2)][ki(64)][lane(32)] -> 4 regs
    for (int idx = tid; idx < 2 * 64 * 32; idx += 256) {
        int lane0 = idx & 31;
        int ki = (idx >> 5) & 63;
        int mt = idx >> 11;
        float hi4[4];
        __nv_bfloat16 lo4[4];
#pragma unroll
        for (int reg = 0; reg < 4; reg++) {
            int rl = mt * 16 + (lane0 >> 2) + 8 * (reg & 1);   // local row 0..31
            int k  = ki * 8 + (lane0 & 3) + 4 * (reg >> 1);    // k 0..511
            int grow = (rl >> 3) * 512 + u0 + (rl & 7);        // q*512 + u0 + uj
            float v = Whh[(size_t)grow * H_DIM + k];
            float h = tf32_hi(v);
            hi4[reg] = h;
            lo4[reg] = __float2bfloat16(v - h);
        }
        ((float4*)w_hi_s)[idx] = make_float4(hi4[0], hi4[1], hi4[2], hi4[3]);
        __nv_bfloat162 p0; p0.x = lo4[0]; p0.y = lo4[1];
        __nv_bfloat162 p1; p1.x = lo4[2]; p1.y = lo4[3];
        uint2 packed;
        packed.x = *(unsigned*)&p0;
        packed.y = *(unsigned*)&p1;
        ((uint2*)w_lo_s)[idx] = packed;
    }
    __syncthreads();

    int lane = tid & 31;
    int warp = tid >> 5;
    int mt = warp & 1;
    int nt = warp >> 1;
    // combine roles
    int uj = tid >> 5;
    int bb = tid & 31;
    int myu = u0 + uj;
    int mylen = len_s[bb];
    float c_reg = 0.0f;

    // h frag index for (myu, bb) — hold-read and producer write
    int h_ki  = myu >> 3;
    int h_reg = (myu >> 2) & 1;
    int h_t   = myu & 3;
    int h_lane = ((bb & 7) << 2) | h_t;
    int h_nt  = bb >> 3;
    int hidx = ((h_nt * 64 + h_ki) * 32 + h_lane) * 2 + h_reg;

    volatile int* vf = g_flags;
    int fbase = dir << 6;   // this direction's 64 flags

    for (int s = 0; s < T_LEN; s++) {
        int t = dir ? (T_LEN - 1 - s) : s;
        int p = s & 1;

        // prefetch G (DRAM) for this step
        const float* Gp = g_G + (size_t)(dir * T_LEN + t) * G_ROWS * BATCH;
        float gq0 = __ldg(Gp + (size_t)(0 * 512 + myu) * BATCH + bb);
        float gq1 = __ldg(Gp + (size_t)(1 * 512 + myu) * BATCH + bb);
        float gq2 = __ldg(Gp + (size_t)(2 * 512 + myu) * BATCH + bb);
        float gq3 = __ldg(Gp + (size_t)(3 * 512 + myu) * BATCH + bb);

        // ---- stage h fragments: pure linear copy (layouts match) ----
        {
            const float4* src = (const float4*)(g_hhi + (dir * 2 + p) * HFRAG);
            float4* dst = (float4*)h_hi_s;
#pragma unroll
            for (int i = 0; i < 16; i++)
                dst[tid + i * 256] = __ldcg(src + tid + i * 256);
            const uint4* srcl = (const uint4*)(g_hlo + (dir * 2 + p) * HFRAG);
            uint4* dstl = (uint4*)h_lo_s;
#pragma unroll
            for (int i = 0; i < 8; i++)
                dstl[tid + i * 256] = __ldcg(srcl + tid + i * 256);
        }
        __syncthreads();

        // ---- tensor-core GEMM: gates[32x32] = W[32x512] * h[512x32] ----
        {
            const float4* aH = (const float4*)w_hi_s + (mt * 64) * 32 + lane;
            const uint2*  aL = (const uint2*) w_lo_s + (mt * 64) * 32 + lane;
            const float2* bH = (const float2*)h_hi_s + (nt * 64) * 32 + lane;
            const unsigned* bL = (const unsigned*)h_lo_s + (nt * 64) * 32 + lane;
            float c0 = 0.f, c1 = 0.f, c2 = 0.f, c3 = 0.f;
#pragma unroll 4
            for (int ki = 0; ki < 64; ki++) {
                float4 ah = aH[ki * 32];
                float2 bh = bH[ki * 32];
                uint2 al = aL[ki * 32];
                unsigned bl = bL[ki * 32];
                __nv_bfloat162 al01 = *(__nv_bfloat162*)&al.x;
                __nv_bfloat162 al23 = *(__nv_bfloat162*)&al.y;
                __nv_bfloat162 bl01 = *(__nv_bfloat162*)&bl;
                float a0l = __bfloat162float(al01.x);
                float a1l = __bfloat162float(al01.y);
                float a2l = __bfloat162float(al23.x);
                float a3l = __bfloat162float(al23.y);
                float b0l = __bfloat162float(bl01.x);
                float b1l = __bfloat162float(bl01.y);
                mma_tf32(c0, c1, c2, c3, ah.x, ah.y, ah.z, ah.w, bh.x, bh.y);
                mma_tf32(c0, c1, c2, c3, ah.x, ah.y, ah.z, ah.w, b0l, b1l);
                mma_tf32(c0, c1, c2, c3, a0l, a1l, a2l, a3l, bh.x, bh.y);
            }
            int g = lane >> 2;
            int col = nt * 8 + (lane & 3) * 2;
            int r0 = mt * 16 + g;
            part[r0 * 33 + col] = c0;
            part[r0 * 33 + col + 1] = c1;
            part[(r0 + 8) * 33 + col] = c2;
            part[(r0 + 8) * 33 + col + 1] = c3;
        }
        __syncthreads();

        // ---- gate combine for (unit uj, batch bb) ----
        {
            float s0 = part[(0 * 8 + uj) * 33 + bb] + gq0;
            float s1 = part[(1 * 8 + uj) * 33 + bb] + gq1;
            float s2 = part[(2 * 8 + uj) * 33 + bb] + gq2;
            float s3 = part[(3 * 8 + uj) * 33 + bb] + gq3;
            float ig = fsig(s0);
            float fg = fsig(s1);
            float gg = ftanh(s2);
            float og = fsig(s3);
            float cn = fg * c_reg + ig * gg;
            float hn = og * ftanh(cn);
            bool m = (t < mylen);
            c_reg = m ? cn : c_reg;
            float hold = h_hi_s[hidx] +
                         __bfloat162float(((__nv_bfloat16*)h_lo_s)[hidx]);
            float hsel = m ? hn : hold;
            // publish h in fragment layout (hi fp32 tf32-rounded + lo bf16)
            float hi = tf32_hi(hsel);
            g_hhi[(dir * 2 + (p ^ 1)) * HFRAG + hidx] = hi;
            g_hlo[(dir * 2 + (p ^ 1)) * HFRAG + hidx] =
                __float2bfloat16(hsel - hi);
            out_s[uj * 33 + bb] = m ? hn : 0.0f;
        }
        __syncthreads();

        // ---- coalesced output writes ----
        {
            int b2 = tid >> 3;
            int uj2 = tid & 7;
            float val = out_s[uj2 * 33 + b2];
            int u2 = u0 + uj2;
            out[OUT_OUTPUTS_OFF + ((size_t)(t * BATCH + b2) * 2 + dir) * H_DIM + u2] = val;
            out[OUT_HIDDEN_OFF + ((size_t)(dir * T_LEN + t) * BATCH + b2) * H_DIM + u2] = val;
        }

        // ---- per-direction barrier: fence, publish flag, poll 64 flags ----
        __threadfence();
        __syncthreads();
        if (tid == 0) vf[bk] = s + 1;
        if (tid < 32) {
            int need = s + 1;
            for (;;) {
                int a = vf[fbase + tid];
                int b_ = vf[fbase + tid + 32];
                if (a >= need && b_ >= need) break;
                __nanosleep(40);
            }
        }
        __syncthreads();
    }
}

// ---------------- launch ----------------
extern "C" void kernel_launch(void* const* d_in, const int* in_sizes, int n_in,
                              void* d_out, int out_size) {
    const int* seq     = (const int*)d_in[0];
    const int* lens    = (const int*)d_in[1];
    const float* emb   = (const float*)d_in[2];
    const float* Wih_f = (const float*)d_in[3];
    const float* Whh_f = (const float*)d_in[4];
    const float* bih_f = (const float*)d_in[5];
    const float* bhh_f = (const float*)d_in[6];
    const float* Wih_b = (const float*)d_in[7];
    const float* Whh_b = (const float*)d_in[8];
    const float* bih_b = (const float*)d_in[9];
    const float* bhh_b = (const float*)d_in[10];
    float* out = (float*)d_out;

    init_kernel<<<256, 256>>>();
    embed_kernel<<<(M_TOT * 128) / 256, 256>>>(seq, emb, out + OUT_EMB_OFF);
    xproj_kernel<<<dim3(G_ROWS / 64, M_TOT / 64, 2), 256>>>(
        seq, emb, Wih_f, Wih_b, bih_f, bhh_f, bih_b, bhh_b);
    cudaFuncSetAttribute(lstm_rec, cudaFuncAttributeMaxDynamicSharedMemorySize,
                         SMEM_BYTES);
    lstm_rec<<<NBLK, 256, SMEM_BYTES>>>(Whh_f, Whh_b, lens, out);
}

// round 5
// speedup vs baseline: 1.6842x; 1.4577x over previous
#include <cuda_runtime.h>
#include <cuda_bf16.h>
#include <cstdint>
#include <cstddef>

// ---------------- problem constants ----------------
#define T_LEN 512
#define BATCH 32
#define H_DIM 512
#define G_ROWS 2048
#define M_TOT (T_LEN * BATCH)           // 16384
#define VOCAB 50000
#define OUT_OUTPUTS_OFF 0
#define OUT_HIDDEN_OFF  16777216
#define OUT_EMB_OFF     33554432
#define NBLK 128
#define HFRAG 16384                     // h bf16 elements per (dir,parity)

// ---------------- device scratch ----------------
__device__ float g_G[(size_t)2 * T_LEN * G_ROWS * BATCH];          // preactivations
__device__ __align__(16) __nv_bfloat16 g_hh[2 * 2 * HFRAG];        // h hi frags
__device__ __align__(16) __nv_bfloat16 g_hl[2 * 2 * HFRAG];        // h lo frags
__device__ int g_flags[NBLK];
__device__ __align__(16) __nv_bfloat16 g_emb_hi[(size_t)VOCAB * H_DIM];
__device__ __align__(16) __nv_bfloat16 g_emb_lo[(size_t)VOCAB * H_DIM];
// Wih fragments: [dir][mtg(128)][ki(32)][lane(32)] uint4
__device__ __align__(16) uint4 g_xwf_hi[2 * 128 * 32 * 32];
__device__ __align__(16) uint4 g_xwf_lo[2 * 128 * 32 * 32];

// ---------------- helpers ----------------
__device__ __forceinline__ unsigned pack_bf16(float x, float y) {
    __nv_bfloat162 t;
    t.x = __float2bfloat16(x);
    t.y = __float2bfloat16(y);
    return *(unsigned*)&t;
}
__device__ __forceinline__ void split_bf16(float v, float& hi, float& lo) {
    hi = __bfloat162float(__float2bfloat16(v));
    lo = v - hi;
}
__device__ __forceinline__ void mma_bf16(float& c0, float& c1, float& c2, float& c3,
                                         unsigned a0, unsigned a1, unsigned a2, unsigned a3,
                                         unsigned b0, unsigned b1) {
    asm volatile(
        "mma.sync.aligned.m16n8k16.row.col.f32.bf16.bf16.f32 "
        "{%0,%1,%2,%3}, {%4,%5,%6,%7}, {%8,%9}, {%0,%1,%2,%3};\n"
        : "+f"(c0), "+f"(c1), "+f"(c2), "+f"(c3)
        : "r"(a0), "r"(a1), "r"(a2), "r"(a3), "r"(b0), "r"(b1));
}
__device__ __forceinline__ float fsig(float x) {
    return __fdividef(1.0f, 1.0f + __expf(-x));
}
__device__ __forceinline__ float ftanh(float x) {
    x = fminf(fmaxf(x, -15.0f), 15.0f);
    float e = __expf(-2.0f * x);
    return __fdividef(1.0f - e, 1.0f + e);
}
__device__ __forceinline__ unsigned smem_u32(const void* p) {
    return (unsigned)__cvta_generic_to_shared(p);
}
#define CP_ASYNC16(dst, src) \
    asm volatile("cp.async.cg.shared.global [%0], [%1], 16;\n" ::"r"(dst), "l"(src))
#define CP_COMMIT() asm volatile("cp.async.commit_group;\n")
#define CP_WAIT(n) asm volatile("cp.async.wait_group %0;\n" ::"n"(n))

// ---------------- init ----------------
__global__ void init_kernel() {
    int tid = blockIdx.x * blockDim.x + threadIdx.x;
    if (tid < 2 * 2 * HFRAG) {
        g_hh[tid] = __float2bfloat16(0.0f);
        g_hl[tid] = __float2bfloat16(0.0f);
    }
    if (tid < NBLK) g_flags[tid] = 0;
}

// ---------------- emb split: fp32 -> bf16 hi/lo ----------------
__global__ void emb_split_kernel(const float* __restrict__ emb) {
    size_t i = (size_t)blockIdx.x * blockDim.x + threadIdx.x;   // over float4s
    float4 v = *(const float4*)(emb + i * 4);
    float h0, l0, h1, l1, h2, l2, h3, l3;
    split_bf16(v.x, h0, l0); split_bf16(v.y, h1, l1);
    split_bf16(v.z, h2, l2); split_bf16(v.w, h3, l3);
    uint2 hp, lp;
    hp.x = pack_bf16(h0, h1); hp.y = pack_bf16(h2, h3);
    lp.x = pack_bf16(l0, l1); lp.y = pack_bf16(l2, l3);
    ((uint2*)g_emb_hi)[i] = hp;
    ((uint2*)g_emb_lo)[i] = lp;
}

// ---------------- Wih fragment prep ----------------
__global__ void xwf_prep_kernel(const float* __restrict__ Wf,
                                const float* __restrict__ Wb) {
    int idx = blockIdx.x * blockDim.x + threadIdx.x;   // 2*128*32*32
    int lane = idx & 31;
    int ki = (idx >> 5) & 31;
    int mtg = (idx >> 10) & 127;
    int dir = idx >> 17;
    const float* W = dir ? Wb : Wf;
    int g = lane >> 2, t = lane & 3;
    int r0 = mtg * 16 + g, r1 = r0 + 8;
    int k0 = ki * 16 + t * 2;
    float h[8], l[8];
    split_bf16(W[(size_t)r0 * H_DIM + k0], h[0], l[0]);
    split_bf16(W[(size_t)r0 * H_DIM + k0 + 1], h[1], l[1]);
    split_bf16(W[(size_t)r1 * H_DIM + k0], h[2], l[2]);
    split_bf16(W[(size_t)r1 * H_DIM + k0 + 1], h[3], l[3]);
    split_bf16(W[(size_t)r0 * H_DIM + k0 + 8], h[4], l[4]);
    split_bf16(W[(size_t)r0 * H_DIM + k0 + 9], h[5], l[5]);
    split_bf16(W[(size_t)r1 * H_DIM + k0 + 8], h[6], l[6]);
    split_bf16(W[(size_t)r1 * H_DIM + k0 + 9], h[7], l[7]);
    uint4 hv, lv;
    hv.x = pack_bf16(h[0], h[1]); hv.y = pack_bf16(h[2], h[3]);
    hv.z = pack_bf16(h[4], h[5]); hv.w = pack_bf16(h[6], h[7]);
    lv.x = pack_bf16(l[0], l[1]); lv.y = pack_bf16(l[2], l[3]);
    lv.z = pack_bf16(l[4], l[5]); lv.w = pack_bf16(l[6], l[7]);
    g_xwf_hi[idx] = hv;
    g_xwf_lo[idx] = lv;
}

// ---------------- embedded output: gather ----------------
__global__ void embed_kernel(const int* __restrict__ seq,
                             const float* __restrict__ emb,
                             float* __restrict__ out_emb) {
    int i = blockIdx.x * blockDim.x + threadIdx.x;
    int m = i >> 7;
    int hq = (i & 127) << 2;
    int row = __ldg(seq + m);
    float4 v = *(const float4*)(emb + (size_t)row * H_DIM + hq);
    *(float4*)(out_emb + (size_t)m * H_DIM + hq) = v;
}

// ---------------- xproj: tensor-core GEMM G = Wih @ x^T + bias ----------------
// M=2048 (gate rows), N=16384 (t*32+b), K=512. 3-term bf16 split.
// Block: 128 rows x 64 cols. 8 warps = 4 mw x 2 nw; warp = m32 x n32.
#define BSTRIDE 56   // halfwords per staged column (conflict-free, 16B-aligned)
__global__ void __launch_bounds__(256, 1) xproj_mma(
    const int* __restrict__ seq,
    const float* __restrict__ bihf, const float* __restrict__ bhhf,
    const float* __restrict__ bihb, const float* __restrict__ bhhb) {
    __shared__ __align__(16) __nv_bfloat16 BsH[2][64 * BSTRIDE];
    __shared__ __align__(16) __nv_bfloat16 BsL[2][64 * BSTRIDE];
    __shared__ int idxs[64];

    int tid = threadIdx.x;
    int n0 = blockIdx.x * 64;
    int m0 = blockIdx.y * 128;
    int dir = blockIdx.z;
    const float* b1 = dir ? bihb : bihf;
    const float* b2 = dir ? bhhb : bhhf;

    if (tid < 64) idxs[tid] = seq[n0 + tid];
    __syncthreads();

    int lane = tid & 31;
    int warp = tid >> 5;
    int mw = warp >> 1;      // 0..3
    int nw = warp & 1;       // 0..1
    int g = lane >> 2, t = lane & 3;

    // staging roles
    int sc = tid >> 2;        // col 0..63
    int sp = tid & 3;         // 16B part 0..3
    int srow = idxs[sc];
    unsigned dstH[2], dstL[2];
    dstH[0] = smem_u32(&BsH[0][sc * BSTRIDE + sp * 8]);
    dstH[1] = smem_u32(&BsH[1][sc * BSTRIDE + sp * 8]);
    dstL[0] = smem_u32(&BsL[0][sc * BSTRIDE + sp * 8]);
    dstL[1] = smem_u32(&BsL[1][sc * BSTRIDE + sp * 8]);

#define STAGE(chunk, buf)                                                          \
    {                                                                              \
        const __nv_bfloat16* sH = g_emb_hi + (size_t)srow * H_DIM + (chunk) * 32 + sp * 8; \
        const __nv_bfloat16* sL = g_emb_lo + (size_t)srow * H_DIM + (chunk) * 32 + sp * 8; \
        CP_ASYNC16(dstH[buf], sH);                                                 \
        CP_ASYNC16(dstL[buf], sL);                                                 \
        CP_COMMIT();                                                               \
    }

    STAGE(0, 0);
    STAGE(1, 1);
    CP_WAIT(1);
    __syncthreads();

    float acc[2][4][4];
#pragma unroll
    for (int a = 0; a < 2; a++)
#pragma unroll
        for (int b = 0; b < 4; b++)
#pragma unroll
            for (int c = 0; c < 4; c++) acc[a][b][c] = 0.0f;

    // A-frag base indices: frag (dir, mtg, ki, lane)
    int mtg0 = (m0 >> 4) + mw * 2;     // 2 m16 frags: mtg0, mtg0+1
    const uint4* AH0 = g_xwf_hi + (((size_t)dir * 128 + mtg0) * 32) * 32 + lane;
    const uint4* AH1 = g_xwf_hi + (((size_t)dir * 128 + mtg0 + 1) * 32) * 32 + lane;
    const uint4* AL0 = g_xwf_lo + (((size_t)dir * 128 + mtg0) * 32) * 32 + lane;
    const uint4* AL1 = g_xwf_lo + (((size_t)dir * 128 + mtg0 + 1) * 32) * 32 + lane;

    uint4 nAH0 = __ldg(AH0), nAH1 = __ldg(AH1);
    uint4 nAL0 = __ldg(AL0), nAL1 = __ldg(AL1);

    for (int chunk = 0; chunk < 16; chunk++) {
        int buf = chunk & 1;
#pragma unroll
        for (int kl = 0; kl < 2; kl++) {
            int ki = chunk * 2 + kl;
            uint4 aH0 = nAH0, aH1 = nAH1, aL0 = nAL0, aL1 = nAL1;
            int kin = (ki + 1 < 32) ? (ki + 1) : 31;
            nAH0 = __ldg(AH0 + kin * 32);
            nAH1 = __ldg(AH1 + kin * 32);
            nAL0 = __ldg(AL0 + kin * 32);
            nAL1 = __ldg(AL1 + kin * 32);
            const unsigned* bh = (const unsigned*)&BsH[buf][0];
            const unsigned* bl = (const unsigned*)&BsL[buf][0];
#pragma unroll
            for (int nf = 0; nf < 4; nf++) {
                int coll = nw * 32 + nf * 8 + g;
                int kloc = kl * 16 + t * 2;
                unsigned bH0 = bh[(coll * BSTRIDE + kloc) >> 1];
                unsigned bH1 = bh[(coll * BSTRIDE + kloc + 8) >> 1];
                unsigned bL0 = bl[(coll * BSTRIDE + kloc) >> 1];
                unsigned bL1 = bl[(coll * BSTRIDE + kloc + 8) >> 1];
                mma_bf16(acc[0][nf][0], acc[0][nf][1], acc[0][nf][2], acc[0][nf][3],
                         aH0.x, aH0.y, aH0.z, aH0.w, bH0, bH1);
                mma_bf16(acc[0][nf][0], acc[0][nf][1], acc[0][nf][2], acc[0][nf][3],
                         aH0.x, aH0.y, aH0.z, aH0.w, bL0, bL1);
                mma_bf16(acc[0][nf][0], acc[0][nf][1], acc[0][nf][2], acc[0][nf][3],
                         aL0.x, aL0.y, aL0.z, aL0.w, bH0, bH1);
                mma_bf16(acc[1][nf][0], acc[1][nf][1], acc[1][nf][2], acc[1][nf][3],
                         aH1.x, aH1.y, aH1.z, aH1.w, bH0, bH1);
                mma_bf16(acc[1][nf][0], acc[1][nf][1], acc[1][nf][2], acc[1][nf][3],
                         aH1.x, aH1.y, aH1.z, aH1.w, bL0, bL1);
                mma_bf16(acc[1][nf][0], acc[1][nf][1], acc[1][nf][2], acc[1][nf][3],
                         aL1.x, aL1.y, aL1.z, aL1.w, bH0, bH1);
            }
        }
        __syncthreads();
        if (chunk + 2 < 16) {
            STAGE(chunk + 2, buf);
            CP_WAIT(1);
        } else {
            CP_WAIT(0);
        }
        __syncthreads();
    }

    // epilogue: bias + write G[dir][t][r][b]
    int tcol = ((n0 + nw * 32) >> 5);
#pragma unroll
    for (int mf = 0; mf < 2; mf++) {
        int r = m0 + mw * 32 + mf * 16 + g;
        float biasA = __ldg(b1 + r) + __ldg(b2 + r);
        float biasB = __ldg(b1 + r + 8) + __ldg(b2 + r + 8);
#pragma unroll
        for (int nf = 0; nf < 4; nf++) {
            int b = nf * 8 + t * 2;
            float2 v0 = make_float2(acc[mf][nf][0] + biasA, acc[mf][nf][1] + biasA);
            float2 v1 = make_float2(acc[mf][nf][2] + biasB, acc[mf][nf][3] + biasB);
            *(float2*)(g_G + (((size_t)(dir * T_LEN + tcol) * G_ROWS + r) * BATCH + b)) = v0;
            *(float2*)(g_G + (((size_t)(dir * T_LEN + tcol) * G_ROWS + r + 8) * BATCH + b)) = v1;
        }
    }
}

// ---------------- persistent recurrence kernel (bf16 3-term mma) ----------------
// smem floats: WHI 8192 | WLO 8192 | HHI 8192 | HLO 8192 | PART 128*33 | OUT 8*33 | LEN 32
#define SM_WHI  0
#define SM_WLO  8192
#define SM_HHI  16384
#define SM_HLO  24576
#define SM_PART 32768
#define SM_OUT  (SM_PART + 128 * 33)
#define SM_LEN  (SM_OUT + 8 * 33)
#define SMEM_FLOATS (SM_LEN + 32)
#define SMEM_BYTES (SMEM_FLOATS * 4)

__global__ void __launch_bounds__(256, 1) lstm_rec(
    const float* __restrict__ Whh_f, const float* __restrict__ Whh_b,
    const int* __restrict__ lengths, float* __restrict__ out) {
    extern __shared__ float sm[];
    float* w_hi_s = sm + SM_WHI;   // uint4 frags [mt(2)][ki(32)][lane(32)]
    float* w_lo_s = sm + SM_WLO;
    float* h_hi_s = sm + SM_HHI;   // uint2 frags [nt(4)][ki(32)][lane(32)]
    float* h_lo_s = sm + SM_HLO;
    float* part   = sm + SM_PART;  // [kc*32 + r][b] padded 33
    float* out_s  = sm + SM_OUT;
    int*   len_s  = (int*)(sm + SM_LEN);

    int tid = threadIdx.x;
    int bk = blockIdx.x;
    int dir = bk >> 6;
    int u0 = (bk & 63) * 8;
    const float* Whh = dir ? Whh_b : Whh_f;

    if (tid < 32) len_s[tid] = lengths[tid];

    // ---- one-time: build W fragments (bf16 hi/lo, m16n8k16 A layout) ----
    for (int idx = tid; idx < 2 * 32 * 32; idx += 256) {
        int lane0 = idx & 31;
        int ki = (idx >> 5) & 31;
        int mt = idx >> 10;
        int g0 = lane0 >> 2, t0 = lane0 & 3;
        int rl0 = mt * 16 + g0, rl1 = rl0 + 8;
        int k0 = ki * 16 + t0 * 2;
        float h[8], l[8];
        int gr0 = (rl0 >> 3) * 512 + u0 + (rl0 & 7);
        int gr1 = (rl1 >> 3) * 512 + u0 + (rl1 & 7);
        split_bf16(Whh[(size_t)gr0 * H_DIM + k0], h[0], l[0]);
        split_bf16(Whh[(size_t)gr0 * H_DIM + k0 + 1], h[1], l[1]);
        split_bf16(Whh[(size_t)gr1 * H_DIM + k0], h[2], l[2]);
        split_bf16(Whh[(size_t)gr1 * H_DIM + k0 + 1], h[3], l[3]);
        split_bf16(Whh[(size_t)gr0 * H_DIM + k0 + 8], h[4], l[4]);
        split_bf16(Whh[(size_t)gr0 * H_DIM + k0 + 9], h[5], l[5]);
        split_bf16(Whh[(size_t)gr1 * H_DIM + k0 + 8], h[6], l[6]);
        split_bf16(Whh[(size_t)gr1 * H_DIM + k0 + 9], h[7], l[7]);
        uint4 hv, lv;
        hv.x = pack_bf16(h[0], h[1]); hv.y = pack_bf16(h[2], h[3]);
        hv.z = pack_bf16(h[4], h[5]); hv.w = pack_bf16(h[6], h[7]);
        lv.x = pack_bf16(l[0], l[1]); lv.y = pack_bf16(l[2], l[3]);
        lv.z = pack_bf16(l[4], l[5]); lv.w = pack_bf16(l[6], l[7]);
        ((uint4*)w_hi_s)[idx] = hv;
        ((uint4*)w_lo_s)[idx] = lv;
    }
    __syncthreads();

    int lane = tid & 31;
    int warp = tid >> 5;
    int mt = warp & 1;
    int kc = warp >> 1;    // 0..3 split-K
    // combine roles
    int uj = tid >> 5;
    int bb = tid & 31;
    int myu = u0 + uj;
    int mylen = len_s[bb];
    float c_reg = 0.0f;

    // h frag element index for (myu, bb)
    int km = myu & 15;
    int h_reg = (km >> 3);
    int h_t = (km >> 1) & 3;
    int h_half = km & 1;
    int h_ki = myu >> 4;
    int h_nt = bb >> 3;
    int h_lane = ((bb & 7) << 2) | h_t;
    int hidx = ((((h_nt * 32 + h_ki) * 32 + h_lane) * 2 + h_reg) << 1) + h_half;

    volatile int* vf = g_flags;
    int fbase = dir << 6;

    for (int s = 0; s < T_LEN; s++) {
        int t = dir ? (T_LEN - 1 - s) : s;
        int p = s & 1;

        const float* Gp = g_G + (size_t)(dir * T_LEN + t) * G_ROWS * BATCH;
        float gq0 = __ldg(Gp + (size_t)(0 * 512 + myu) * BATCH + bb);
        float gq1 = __ldg(Gp + (size_t)(1 * 512 + myu) * BATCH + bb);
        float gq2 = __ldg(Gp + (size_t)(2 * 512 + myu) * BATCH + bb);
        float gq3 = __ldg(Gp + (size_t)(3 * 512 + myu) * BATCH + bb);

        // ---- stage h fragments (linear bf16 copy, 64 KB total) ----
        {
            const uint4* srcH = (const uint4*)(g_hh + (dir * 2 + p) * HFRAG);
            const uint4* srcL = (const uint4*)(g_hl + (dir * 2 + p) * HFRAG);
            uint4* dH = (uint4*)h_hi_s;
            uint4* dL = (uint4*)h_lo_s;
#pragma unroll
            for (int i = 0; i < 8; i++) {
                dH[tid + i * 256] = __ldcg(srcH + tid + i * 256);
                dL[tid + i * 256] = __ldcg(srcL + tid + i * 256);
            }
        }
        __syncthreads();

        // ---- bf16 mma GEMM: per warp m16 x n32 x k128 ----
        {
            float acc[4][4];
#pragma unroll
            for (int a = 0; a < 4; a++)
#pragma unroll
                for (int b = 0; b < 4; b++) acc[a][b] = 0.0f;
            const uint4* AH = (const uint4*)w_hi_s + (mt * 32) * 32 + lane;
            const uint4* AL = (const uint4*)w_lo_s + (mt * 32) * 32 + lane;
            const uint2* BH = (const uint2*)h_hi_s + lane;
            const uint2* BL = (const uint2*)h_lo_s + lane;
#pragma unroll 2
            for (int kio = 0; kio < 8; kio++) {
                int ki = kc * 8 + kio;
                uint4 ah = AH[ki * 32];
                uint4 al = AL[ki * 32];
#pragma unroll
                for (int nt = 0; nt < 4; nt++) {
                    uint2 bh = BH[(nt * 32 + ki) * 32];
                    uint2 bl = BL[(nt * 32 + ki) * 32];
                    mma_bf16(acc[nt][0], acc[nt][1], acc[nt][2], acc[nt][3],
                             ah.x, ah.y, ah.z, ah.w, bh.x, bh.y);
                    mma_bf16(acc[nt][0], acc[nt][1], acc[nt][2], acc[nt][3],
                             ah.x, ah.y, ah.z, ah.w, bl.x, bl.y);
                    mma_bf16(acc[nt][0], acc[nt][1], acc[nt][2], acc[nt][3],
                             al.x, al.y, al.z, al.w, bh.x, bh.y);
                }
            }
            int g0 = lane >> 2, t0 = lane & 3;
#pragma unroll
            for (int nt = 0; nt < 4; nt++) {
                int b = nt * 8 + t0 * 2;
                int r = mt * 16 + g0;
                part[(kc * 32 + r) * 33 + b] = acc[nt][0];
                part[(kc * 32 + r) * 33 + b + 1] = acc[nt][1];
                part[(kc * 32 + r + 8) * 33 + b] = acc[nt][2];
                part[(kc * 32 + r + 8) * 33 + b + 1] = acc[nt][3];
            }
        }
        __syncthreads();

        // ---- gate combine ----
        {
            float s0 = gq0, s1 = gq1, s2 = gq2, s3 = gq3;
#pragma unroll
            for (int kk = 0; kk < 4; kk++) {
                s0 += part[(kk * 32 + 0 * 8 + uj) * 33 + bb];
                s1 += part[(kk * 32 + 1 * 8 + uj) * 33 + bb];
                s2 += part[(kk * 32 + 2 * 8 + uj) * 33 + bb];
                s3 += part[(kk * 32 + 3 * 8 + uj) * 33 + bb];
            }
            float ig = fsig(s0);
            float fg = fsig(s1);
            float gg = ftanh(s2);
            float og = fsig(s3);
            float cn = fg * c_reg + ig * gg;
            float hn = og * ftanh(cn);
            bool m = (t < mylen);
            c_reg = m ? cn : c_reg;
            float hold = __bfloat162float(((__nv_bfloat16*)h_hi_s)[hidx]) +
                         __bfloat162float(((__nv_bfloat16*)h_lo_s)[hidx]);
            float hsel = m ? hn : hold;
            float hi, lo;
            split_bf16(hsel, hi, lo);
            int hbase = (dir * 2 + (p ^ 1)) * HFRAG;
            g_hh[hbase + hidx] = __float2bfloat16(hi);
            g_hl[hbase + hidx] = __float2bfloat16(lo);
            out_s[uj * 33 + bb] = m ? hn : 0.0f;
        }
        __syncthreads();

        // ---- coalesced output writes ----
        {
            int b2 = tid >> 3;
            int uj2 = tid & 7;
            float val = out_s[uj2 * 33 + b2];
            int u2 = u0 + uj2;
            out[OUT_OUTPUTS_OFF + ((size_t)(t * BATCH + b2) * 2 + dir) * H_DIM + u2] = val;
            out[OUT_HIDDEN_OFF + ((size_t)(dir * T_LEN + t) * BATCH + b2) * H_DIM + u2] = val;
        }

        // ---- per-direction barrier ----
        __threadfence();
        __syncthreads();
        if (tid == 0) vf[bk] = s + 1;
        if (tid < 32) {
            int need = s + 1;
            for (;;) {
                int a = vf[fbase + tid];
                int b_ = vf[fbase + tid + 32];
                if (a >= need && b_ >= need) break;
                __nanosleep(40);
            }
        }
        __syncthreads();
    }
}

// ---------------- launch ----------------
extern "C" void kernel_launch(void* const* d_in, const int* in_sizes, int n_in,
                              void* d_out, int out_size) {
    const int* seq     = (const int*)d_in[0];
    const int* lens    = (const int*)d_in[1];
    const float* emb   = (const float*)d_in[2];
    const float* Wih_f = (const float*)d_in[3];
    const float* Whh_f = (const float*)d_in[4];
    const float* bih_f = (const float*)d_in[5];
    const float* bhh_f = (const float*)d_in[6];
    const float* Wih_b = (const float*)d_in[7];
    const float* Whh_b = (const float*)d_in[8];
    const float* bih_b = (const float*)d_in[9];
    const float* bhh_b = (const float*)d_in[10];
    float* out = (float*)d_out;

    init_kernel<<<256, 256>>>();
    emb_split_kernel<<<(VOCAB * H_DIM / 4) / 256, 256>>>(emb);
    xwf_prep_kernel<<<(2 * 128 * 32 * 32) / 256, 256>>>(Wih_f, Wih_b);
    embed_kernel<<<(M_TOT * 128) / 256, 256>>>(seq, emb, out + OUT_EMB_OFF);
    xproj_mma<<<dim3(M_TOT / 64, G_ROWS / 128, 2), 256>>>(
        seq, bih_f, bhh_f, bih_b, bhh_b);
    cudaFuncSetAttribute(lstm_rec, cudaFuncAttributeMaxDynamicSharedMemorySize,
                         SMEM_BYTES);
    lstm_rec<<<NBLK, 256, SMEM_BYTES>>>(Whh_f, Whh_b, lens, out);
}